// round 8
// baseline (speedup 1.0000x reference)
#include <cuda_runtime.h>

#define NTHREADS 256
#define PRIME_X 73856093u
#define PRIME_Y 19349663u
#define PRIME_Z 83492791u

// ---------------- SMEM layout (floats) ----------------
constexpr int OFF_T0 = 0;                    // 50 x 32
constexpr int OFF_T1 = OFF_T0 + 50 * 32;     // 200 x 16
constexpr int OFF_T2 = OFF_T1 + 200 * 16;    // 400 x 8
constexpr int OFF_T3 = OFF_T2 + 400 * 8;     // 400 x 4
constexpr int OFF_T4 = OFF_T3 + 400 * 4;     // 400 x 3 padded to 4
constexpr int OFF_TEND = OFF_T4 + 400 * 4;   // 11200
constexpr int OFF_W1D = OFF_TEND;            // 63 x 64, column-PERMUTED
constexpr int OFF_W1C = OFF_W1D + 63 * 64;
constexpr int OFF_B1D = OFF_W1C + 63 * 64;   // 64 permuted
constexpr int OFF_B1C = OFF_B1D + 64;
constexpr int OFF_W2D = OFF_B1C + 64;        // 64 permuted
constexpr int OFF_W2C = OFF_W2D + 64;        // 3 x 64 permuted
constexpr int FT_STRIDE = 132;               // 128 pts + 4 pad
constexpr int OFF_FT = OFF_W2C + 3 * 64;     // 63 x 132
constexpr int SMEM_FLOATS = OFF_FT + 63 * FT_STRIDE;  // 27964
constexpr int SMEM_BYTES = SMEM_FLOATS * 4;           // ~109.2 KB -> 2 CTA/SM

__device__ __forceinline__ unsigned long long pk2(float a, float b) {
    unsigned long long r;
    asm("mov.b64 %0, {%1, %2};" : "=l"(r) : "f"(a), "f"(b));
    return r;
}
__device__ __forceinline__ void fma2(unsigned long long& d, unsigned long long a,
                                     unsigned long long b) {
    asm("fma.rn.f32x2 %0, %1, %2, %0;" : "+l"(d) : "l"(a), "l"(b));
}
__device__ __forceinline__ void upk2(unsigned long long v, float& a, float& b) {
    asm("mov.b64 {%0, %1}, %2;" : "=f"(a), "=f"(b) : "l"(v));
}

// Stored position p (0..63) -> logical hidden column. Threads cg load positions
// cg*4..+3 and 32+cg*4..+3 conflict-free; same perm applied to W1/b1/W2.
__device__ __forceinline__ int perm_col(int p) {
    int g = (p & 31) >> 2;
    int s = (p < 32) ? (p & 3) : 4 + (p & 3);
    return g * 8 + s;
}

// ---------------- hash-grid encode (LDS.128 gathers) ------------------------
template <int H, int D, int S, int BASE, int FN>
__device__ __forceinline__ void encode_level(const float* __restrict__ sT,
                                             float px, float py, float pz,
                                             float (&feat)[FN]) {
    float fx = floorf(px), fy = floorf(py), fz = floorf(pz);
    float rx = px - fx, ry = py - fy, rz = pz - fz;
    int fxi = (int)fx, fyi = (int)fy, fzi = (int)fz;
    int cxi = (int)ceilf(px), cyi = (int)ceilf(py), czi = (int)ceilf(pz);

    int hx0 = (int)((unsigned)fxi * PRIME_X);
    int hx1 = (int)((unsigned)cxi * PRIME_X);
    int hy0 = (int)((unsigned)fyi * PRIME_Y);
    int hy1 = (int)((unsigned)cyi * PRIME_Y);
    int hz0 = (int)((unsigned)fzi * PRIME_Z);
    int hz1 = (int)((unsigned)czi * PRIME_Z);

    // reference quirk: FLOOR corner weighted by r, CEIL corner by (1-r)
    float wx0 = rx, wx1 = 1.0f - rx;
    float wy0 = ry, wy1 = 1.0f - ry;
    float wz0 = rz, wz1 = 1.0f - rz;

    constexpr int D4 = (D + 3) / 4;
#pragma unroll
    for (int c = 0; c < 8; c++) {
        const int bi = (c >> 2) & 1, bj = (c >> 1) & 1, bk = c & 1;
        int v = (bi ? hx1 : hx0) ^ (bj ? hy1 : hy0) ^ (bk ? hz1 : hz0);
        int h = v % H;
        if (h < 0) h += H;  // Python-style nonneg mod
        float w = (bi ? wx1 : wx0) * (bj ? wy1 : wy0) * (bk ? wz1 : wz0);
        const float4* row = (const float4*)(sT + h * S);
#pragma unroll
        for (int q = 0; q < D4; q++) {
            float4 rv = row[q];
            feat[BASE + 4 * q + 0] = fmaf(w, rv.x, feat[BASE + 4 * q + 0]);
            if (4 * q + 1 < D) feat[BASE + 4 * q + 1] = fmaf(w, rv.y, feat[BASE + 4 * q + 1]);
            if (4 * q + 2 < D) feat[BASE + 4 * q + 2] = fmaf(w, rv.z, feat[BASE + 4 * q + 2]);
            if (4 * q + 3 < D) feat[BASE + 4 * q + 3] = fmaf(w, rv.w, feat[BASE + 4 * q + 3]);
        }
    }
}

// ---------------- GEMM: 4-pt x 8-col tile, acc over column pairs ------------
__device__ __forceinline__ void gemm4(const float* __restrict__ sm,
                                      int W1o, int B1o, int pg, int cg,
                                      unsigned long long (&acc)[4][4]) {
    const ulonglong2 blo = *(const ulonglong2*)(sm + B1o + cg * 4);
    const ulonglong2 bhi = *(const ulonglong2*)(sm + B1o + 32 + cg * 4);
#pragma unroll
    for (int p = 0; p < 4; p++) {
        acc[p][0] = blo.x; acc[p][1] = blo.y; acc[p][2] = bhi.x; acc[p][3] = bhi.y;
    }
    const float4* Ap = ((const float4*)(sm + OFF_FT)) + pg;
    const float* Wp = sm + W1o + cg * 4;
#pragma unroll 9
    for (int k = 0; k < 63; k++) {
        const float4 a = Ap[k * (FT_STRIDE / 4)];
        const ulonglong2 wlo = *(const ulonglong2*)(Wp + k * 64);
        const ulonglong2 whi = *(const ulonglong2*)(Wp + k * 64 + 32);
        unsigned long long ab[4];
        ab[0] = pk2(a.x, a.x); ab[1] = pk2(a.y, a.y);
        ab[2] = pk2(a.z, a.z); ab[3] = pk2(a.w, a.w);
#pragma unroll
        for (int p = 0; p < 4; p++) {
            fma2(acc[p][0], ab[p], wlo.x);
            fma2(acc[p][1], ab[p], wlo.y);
            fma2(acc[p][2], ab[p], whi.x);
            fma2(acc[p][3], ab[p], whi.y);
        }
    }
}

template <int H, int D, int S>
__device__ __forceinline__ void load_table(float* dst, const float* __restrict__ src,
                                           int tid) {
    for (int i = tid; i < H * D; i += NTHREADS) {
        int r = i / D, c = i - r * D;
        dst[r * S + c] = src[i];
    }
}

__global__ void __launch_bounds__(NTHREADS, 2)
nerf_fused_kernel(const float* __restrict__ x, const float* __restrict__ e0,
                  const float* __restrict__ e1, const float* __restrict__ e2,
                  const float* __restrict__ e3, const float* __restrict__ e4,
                  const float* __restrict__ Wd1, const float* __restrict__ bd1,
                  const float* __restrict__ Wd2, const float* __restrict__ bd2,
                  const float* __restrict__ Wc1, const float* __restrict__ bc1,
                  const float* __restrict__ Wc2, const float* __restrict__ bc2,
                  float* __restrict__ out, int N) {
    extern __shared__ float sm[];
    const int tid = threadIdx.x;

    // ---- cooperative SMEM fill ----
    load_table<50, 32, 32>(sm + OFF_T0, e0, tid);
    load_table<200, 16, 16>(sm + OFF_T1, e1, tid);
    load_table<400, 8, 8>(sm + OFF_T2, e2, tid);
    load_table<400, 4, 4>(sm + OFF_T3, e3, tid);
    load_table<400, 3, 4>(sm + OFF_T4, e4, tid);
    for (int i = tid; i < 63 * 64; i += NTHREADS) {
        int k = i >> 6, p = i & 63, o = perm_col(p);
        sm[OFF_W1D + i] = (o < 63) ? Wd1[k * 63 + o] : 0.0f;
        sm[OFF_W1C + i] = (o < 63) ? Wc1[k * 63 + o] : 0.0f;
    }
    for (int p = tid; p < 64; p += NTHREADS) {
        int o = perm_col(p);
        sm[OFF_B1D + p] = (o < 63) ? bd1[o] : 0.0f;
        sm[OFF_B1C + p] = (o < 63) ? bc1[o] : 0.0f;
        sm[OFF_W2D + p] = (o < 63) ? Wd2[o] : 0.0f;
    }
    for (int i = tid; i < 3 * 64; i += NTHREADS) {
        int ch = i >> 6, p = i & 63, o = perm_col(p);
        sm[OFF_W2C + i] = (o < 63) ? Wc2[o * 3 + ch] : 0.0f;
    }
    __syncthreads();

    const int pt_local = tid & 127;
    const int role = tid >> 7;      // warps 0-3: level 0; warps 4-7: levels 1-4
    const int pg = tid >> 3;        // 0..31 -> 4 points each
    const int cg = tid & 7;         // 8 hidden-col group

#pragma unroll 1
    for (int pass = 0; pass < 2; pass++) {
        // ---- phase 1: warp-specialized encode of 128 points ----
        const int pt = blockIdx.x * 256 + pass * 128 + pt_local;
        const int lp = (pt < N) ? pt : 0;
        const float xv = x[lp * 3 + 0];
        const float yv = x[lp * 3 + 1];
        const float zv = x[lp * 3 + 2];

        if (role == 0) {
            float f0[32];
#pragma unroll
            for (int i = 0; i < 32; i++) f0[i] = 0.0f;
            encode_level<50, 32, 32, 0, 32>(sm + OFF_T0, xv, yv, zv, f0);
#pragma unroll
            for (int k = 0; k < 32; k++) sm[OFF_FT + k * FT_STRIDE + pt_local] = f0[k];
        } else {
            float f1[31];
#pragma unroll
            for (int i = 0; i < 31; i++) f1[i] = 0.0f;
            encode_level<200, 16, 16, 0, 31>(sm + OFF_T1, xv * 2.0f, yv * 2.0f, zv * 2.0f, f1);
            encode_level<400, 8, 8, 16, 31>(sm + OFF_T2, xv * 4.0f, yv * 4.0f, zv * 4.0f, f1);
            encode_level<400, 4, 4, 24, 31>(sm + OFF_T3, xv * 8.0f, yv * 8.0f, zv * 8.0f, f1);
            encode_level<400, 3, 4, 28, 31>(sm + OFF_T4, __fdiv_rn(xv, 0.05f),
                                            __fdiv_rn(yv, 0.05f), __fdiv_rn(zv, 0.05f), f1);
#pragma unroll
            for (int k = 0; k < 31; k++)
                sm[OFF_FT + (32 + k) * FT_STRIDE + pt_local] = f1[k];
        }
        __syncthreads();

        const int base_pt = blockIdx.x * 256 + pass * 128 + pg * 4;

        // ===== head D =====
        {
            unsigned long long acc[4][4];
            gemm4(sm, OFF_W1D, OFF_B1D, pg, cg, acc);

            const float4 wlo4 = *(const float4*)(sm + OFF_W2D + cg * 4);
            const float4 whi4 = *(const float4*)(sm + OFF_W2D + 32 + cg * 4);
            const float wq[8] = {wlo4.x, wlo4.y, wlo4.z, wlo4.w,
                                 whi4.x, whi4.y, whi4.z, whi4.w};
            float pd[4] = {0.0f, 0.0f, 0.0f, 0.0f};
#pragma unroll
            for (int p = 0; p < 4; p++) {
#pragma unroll
                for (int cp = 0; cp < 4; cp++) {
                    float h0, h1;
                    upk2(acc[p][cp], h0, h1);
                    pd[p] = fmaf(fmaxf(h0, 0.0f), wq[2 * cp + 0], pd[p]);
                    pd[p] = fmaf(fmaxf(h1, 0.0f), wq[2 * cp + 1], pd[p]);
                }
            }
#pragma unroll
            for (int p = 0; p < 4; p++) {
                pd[p] += __shfl_xor_sync(0xffffffffu, pd[p], 1);
                pd[p] += __shfl_xor_sync(0xffffffffu, pd[p], 2);
                pd[p] += __shfl_xor_sync(0xffffffffu, pd[p], 4);
            }
            if (cg == 0) {
                const float b2 = bd2[0];
#pragma unroll
                for (int p = 0; p < 4; p++) {
                    int o = base_pt + p;
                    if (o < N) out[o] = pd[p] + b2;
                }
            }
        }

        // ===== head C =====
        {
            unsigned long long acc[4][4];
            gemm4(sm, OFF_W1C, OFF_B1C, pg, cg, acc);

            float wq[3][8];
#pragma unroll
            for (int ch = 0; ch < 3; ch++) {
                const float4 wlo4 = *(const float4*)(sm + OFF_W2C + ch * 64 + cg * 4);
                const float4 whi4 = *(const float4*)(sm + OFF_W2C + ch * 64 + 32 + cg * 4);
                wq[ch][0] = wlo4.x; wq[ch][1] = wlo4.y; wq[ch][2] = wlo4.z; wq[ch][3] = wlo4.w;
                wq[ch][4] = whi4.x; wq[ch][5] = whi4.y; wq[ch][6] = whi4.z; wq[ch][7] = whi4.w;
            }
            float pc[3][4];
#pragma unroll
            for (int ch = 0; ch < 3; ch++)
#pragma unroll
                for (int p = 0; p < 4; p++) pc[ch][p] = 0.0f;

#pragma unroll
            for (int p = 0; p < 4; p++) {
#pragma unroll
                for (int cp = 0; cp < 4; cp++) {
                    float h0, h1;
                    upk2(acc[p][cp], h0, h1);
                    h0 = fmaxf(h0, 0.0f);
                    h1 = fmaxf(h1, 0.0f);
#pragma unroll
                    for (int ch = 0; ch < 3; ch++) {
                        pc[ch][p] = fmaf(h0, wq[ch][2 * cp + 0], pc[ch][p]);
                        pc[ch][p] = fmaf(h1, wq[ch][2 * cp + 1], pc[ch][p]);
                    }
                }
            }
#pragma unroll
            for (int ch = 0; ch < 3; ch++)
#pragma unroll
                for (int p = 0; p < 4; p++) {
                    pc[ch][p] += __shfl_xor_sync(0xffffffffu, pc[ch][p], 1);
                    pc[ch][p] += __shfl_xor_sync(0xffffffffu, pc[ch][p], 2);
                    pc[ch][p] += __shfl_xor_sync(0xffffffffu, pc[ch][p], 4);
                }
            if (cg == 0) {
                const float c0 = bc2[0], c1 = bc2[1], c2 = bc2[2];
#pragma unroll
                for (int p = 0; p < 4; p++) {
                    int o = base_pt + p;
                    if (o < N) {
                        out[N + o * 3 + 0] = pc[0][p] + c0;
                        out[N + o * 3 + 1] = pc[1][p] + c1;
                        out[N + o * 3 + 2] = pc[2][p] + c2;
                    }
                }
            }
        }
        __syncthreads();  // FT reusable for next pass
    }
}

extern "C" void kernel_launch(void* const* d_in, const int* in_sizes, int n_in,
                              void* d_out, int out_size) {
    const float* x = (const float*)d_in[0];
    const float* e0 = (const float*)d_in[1];
    const float* e1 = (const float*)d_in[2];
    const float* e2 = (const float*)d_in[3];
    const float* e3 = (const float*)d_in[4];
    const float* e4 = (const float*)d_in[5];
    const float* Wd1 = (const float*)d_in[6];
    const float* bd1 = (const float*)d_in[7];
    const float* Wd2 = (const float*)d_in[8];
    const float* bd2 = (const float*)d_in[9];
    const float* Wc1 = (const float*)d_in[10];
    const float* bc1 = (const float*)d_in[11];
    const float* Wc2 = (const float*)d_in[12];
    const float* bc2 = (const float*)d_in[13];

    const int N = in_sizes[0] / 3;
    float* out = (float*)d_out;

    cudaFuncSetAttribute(nerf_fused_kernel,
                         cudaFuncAttributeMaxDynamicSharedMemorySize, SMEM_BYTES);

    const int grid = (N + 255) / 256;
    nerf_fused_kernel<<<grid, NTHREADS, SMEM_BYTES>>>(
        x, e0, e1, e2, e3, e4, Wd1, bd1, Wd2, bd2, Wc1, bc1, Wc2, bc2, out, N);
}

// round 10
// speedup vs baseline: 1.1963x; 1.1963x over previous
#include <cuda_runtime.h>

#define NTHREADS 256
#define PTS 256
#define PRIME_X 73856093u
#define PRIME_Y 19349663u
#define PRIME_Z 83492791u

// ---------------- SMEM layout (floats) ----------------
constexpr int OFF_T0 = 0;                    // 50 x 32, stride 36
constexpr int OFF_T1 = OFF_T0 + 50 * 36;     // 200 x 16, stride 20
constexpr int OFF_T2 = OFF_T1 + 200 * 20;    // 400 x 8,  stride 12
constexpr int OFF_T3 = OFF_T2 + 400 * 12;    // 400 x 4,  stride 4
constexpr int OFF_T4 = OFF_T3 + 400 * 4;     // 400 x 3,  stride 4 (pad)
constexpr int OFF_TEND = OFF_T4 + 400 * 4;   // 13800
constexpr int OFF_W1D = OFF_TEND;            // 63 x 64 (col 63 zero)
constexpr int OFF_W1C = OFF_W1D + 63 * 64;
constexpr int OFF_B1D = OFF_W1C + 63 * 64;   // 64
constexpr int OFF_B1C = OFF_B1D + 64;
constexpr int OFF_W2D = OFF_B1C + 64;        // 64
constexpr int OFF_W2C = OFF_W2D + 64;        // 3 x 64 (transposed)
constexpr int FT_STRIDE = PTS + 8;           // 264
constexpr int OFF_FT = OFF_W2C + 3 * 64;     // 63 x 264 transposed features
constexpr int SMEM_FLOATS = OFF_FT + 63 * FT_STRIDE;
constexpr int SMEM_BYTES = SMEM_FLOATS * 4;  // ~155.5 KB

__device__ __forceinline__ unsigned long long pk2(float a, float b) {
    unsigned long long r;
    asm("mov.b64 %0, {%1, %2};" : "=l"(r) : "f"(a), "f"(b));
    return r;
}
__device__ __forceinline__ void fma2(unsigned long long& d, unsigned long long a,
                                     unsigned long long b) {
    asm("fma.rn.f32x2 %0, %1, %2, %0;" : "+l"(d) : "l"(a), "l"(b));
}
__device__ __forceinline__ void upk2(unsigned long long v, float& a, float& b) {
    asm("mov.b64 {%0, %1}, %2;" : "=f"(a), "=f"(b) : "l"(v));
}

// ---------------- hash-grid encode (LDS.128 gathers, full unroll) -----------
template <int H, int D, int S, int BASE>
__device__ __forceinline__ void encode_level(const float* __restrict__ sT,
                                             float px, float py, float pz,
                                             float (&feat)[63]) {
    float fx = floorf(px), fy = floorf(py), fz = floorf(pz);
    float rx = px - fx, ry = py - fy, rz = pz - fz;
    int fxi = (int)fx, fyi = (int)fy, fzi = (int)fz;
    int cxi = (int)ceilf(px), cyi = (int)ceilf(py), czi = (int)ceilf(pz);

    int hx0 = (int)((unsigned)fxi * PRIME_X);
    int hx1 = (int)((unsigned)cxi * PRIME_X);
    int hy0 = (int)((unsigned)fyi * PRIME_Y);
    int hy1 = (int)((unsigned)cyi * PRIME_Y);
    int hz0 = (int)((unsigned)fzi * PRIME_Z);
    int hz1 = (int)((unsigned)czi * PRIME_Z);

    // reference quirk: FLOOR corner weighted by r, CEIL corner by (1-r)
    float wx0 = rx, wx1 = 1.0f - rx;
    float wy0 = ry, wy1 = 1.0f - ry;
    float wz0 = rz, wz1 = 1.0f - rz;

    constexpr int D4 = (D + 3) / 4;
#pragma unroll
    for (int c = 0; c < 8; c++) {
        const int bi = (c >> 2) & 1, bj = (c >> 1) & 1, bk = c & 1;
        int v = (bi ? hx1 : hx0) ^ (bj ? hy1 : hy0) ^ (bk ? hz1 : hz0);
        int h = v % H;
        if (h < 0) h += H;  // Python-style nonneg mod
        float w = (bi ? wx1 : wx0) * (bj ? wy1 : wy0) * (bk ? wz1 : wz0);
        const float4* row = (const float4*)(sT + h * S);
#pragma unroll
        for (int q = 0; q < D4; q++) {
            float4 rv = row[q];
            feat[BASE + 4 * q + 0] = fmaf(w, rv.x, feat[BASE + 4 * q + 0]);
            if (4 * q + 1 < D) feat[BASE + 4 * q + 1] = fmaf(w, rv.y, feat[BASE + 4 * q + 1]);
            if (4 * q + 2 < D) feat[BASE + 4 * q + 2] = fmaf(w, rv.z, feat[BASE + 4 * q + 2]);
            if (4 * q + 3 < D) feat[BASE + 4 * q + 3] = fmaf(w, rv.w, feat[BASE + 4 * q + 3]);
        }
    }
}

// -------- fused dual-head GEMM: one A stream feeds both weight sets --------
// Thread tile: 8 points (pg) x 8 cols (cg), acc f32x2 over point pairs.
__device__ __forceinline__ void gemm_tile2(const float* __restrict__ smem,
                                           int pg, int cg,
                                           unsigned long long (&accD)[4][8],
                                           unsigned long long (&accC)[4][8]) {
#pragma unroll
    for (int half = 0; half < 2; half++) {
        const float4* bD4 = (const float4*)(smem + OFF_B1D + cg * 8 + half * 4);
        const float4* bC4 = (const float4*)(smem + OFF_B1C + cg * 8 + half * 4);
        float4 bD = bD4[0], bC = bC4[0];
        float dD[4] = {bD.x, bD.y, bD.z, bD.w};
        float dC[4] = {bC.x, bC.y, bC.z, bC.w};
#pragma unroll
        for (int c = 0; c < 4; c++) {
            unsigned long long pD = pk2(dD[c], dD[c]);
            unsigned long long pC = pk2(dC[c], dC[c]);
#pragma unroll
            for (int pp = 0; pp < 4; pp++) {
                accD[pp][half * 4 + c] = pD;
                accC[pp][half * 4 + c] = pC;
            }
        }
    }
    const float4* Ap = (const float4*)(smem + OFF_FT + pg * 8);
    const float4* BD = (const float4*)(smem + OFF_W1D + cg * 8);
    const float4* BC = (const float4*)(smem + OFF_W1C + cg * 8);
#pragma unroll 9
    for (int k = 0; k < 63; k++) {
        const float4 a_lo = Ap[k * (FT_STRIDE / 4) + 0];
        const float4 a_hi = Ap[k * (FT_STRIDE / 4) + 1];
        const float4 wd_lo = BD[k * 16 + 0];
        const float4 wd_hi = BD[k * 16 + 1];
        const float4 wc_lo = BC[k * 16 + 0];
        const float4 wc_hi = BC[k * 16 + 1];
        unsigned long long aP[4];
        aP[0] = pk2(a_lo.x, a_lo.y);
        aP[1] = pk2(a_lo.z, a_lo.w);
        aP[2] = pk2(a_hi.x, a_hi.y);
        aP[3] = pk2(a_hi.z, a_hi.w);
        float wd[8] = {wd_lo.x, wd_lo.y, wd_lo.z, wd_lo.w,
                       wd_hi.x, wd_hi.y, wd_hi.z, wd_hi.w};
        float wc[8] = {wc_lo.x, wc_lo.y, wc_lo.z, wc_lo.w,
                       wc_hi.x, wc_hi.y, wc_hi.z, wc_hi.w};
#pragma unroll
        for (int c = 0; c < 8; c++) {
            const unsigned long long bD2 = pk2(wd[c], wd[c]);
            const unsigned long long bC2 = pk2(wc[c], wc[c]);
            fma2(accD[0][c], aP[0], bD2);
            fma2(accD[1][c], aP[1], bD2);
            fma2(accD[2][c], aP[2], bD2);
            fma2(accD[3][c], aP[3], bD2);
            fma2(accC[0][c], aP[0], bC2);
            fma2(accC[1][c], aP[1], bC2);
            fma2(accC[2][c], aP[2], bC2);
            fma2(accC[3][c], aP[3], bC2);
        }
    }
}

template <int H, int D, int S>
__device__ __forceinline__ void load_table(float* dst, const float* __restrict__ src,
                                           int tid) {
    for (int i = tid; i < H * D; i += NTHREADS) {
        int r = i / D, c = i - r * D;
        dst[r * S + c] = src[i];
    }
}

__global__ void __launch_bounds__(NTHREADS, 1)
nerf_fused_kernel(const float* __restrict__ x, const float* __restrict__ e0,
                  const float* __restrict__ e1, const float* __restrict__ e2,
                  const float* __restrict__ e3, const float* __restrict__ e4,
                  const float* __restrict__ Wd1, const float* __restrict__ bd1,
                  const float* __restrict__ Wd2, const float* __restrict__ bd2,
                  const float* __restrict__ Wc1, const float* __restrict__ bc1,
                  const float* __restrict__ Wc2, const float* __restrict__ bc2,
                  float* __restrict__ out, int N) {
    extern __shared__ float sm[];
    const int tid = threadIdx.x;

    // ---- cooperative SMEM fill ----
    load_table<50, 32, 36>(sm + OFF_T0, e0, tid);
    load_table<200, 16, 20>(sm + OFF_T1, e1, tid);
    load_table<400, 8, 12>(sm + OFF_T2, e2, tid);
    load_table<400, 4, 4>(sm + OFF_T3, e3, tid);
    load_table<400, 3, 4>(sm + OFF_T4, e4, tid);
    for (int i = tid; i < 63 * 64; i += NTHREADS) {
        int j = i >> 6, o = i & 63;
        sm[OFF_W1D + i] = (o < 63) ? Wd1[j * 63 + o] : 0.0f;
        sm[OFF_W1C + i] = (o < 63) ? Wc1[j * 63 + o] : 0.0f;
    }
    for (int i = tid; i < 64; i += NTHREADS) {
        sm[OFF_B1D + i] = (i < 63) ? bd1[i] : 0.0f;
        sm[OFF_B1C + i] = (i < 63) ? bc1[i] : 0.0f;
        sm[OFF_W2D + i] = (i < 63) ? Wd2[i] : 0.0f;
    }
    for (int i = tid; i < 3 * 64; i += NTHREADS) {
        int ch = i >> 6, o = i & 63;
        sm[OFF_W2C + i] = (o < 63) ? Wc2[o * 3 + ch] : 0.0f;
    }
    __syncthreads();

    // ---- phase 1: encode own point, stage transposed features ----
    const int idx = blockIdx.x * PTS + tid;
    const int lidx = (idx < N) ? idx : 0;
    const float xv = x[lidx * 3 + 0];
    const float yv = x[lidx * 3 + 1];
    const float zv = x[lidx * 3 + 2];

    float feat[63];
#pragma unroll
    for (int i = 0; i < 63; i++) feat[i] = 0.0f;
    encode_level<50, 32, 36, 0>(sm + OFF_T0, xv, yv, zv, feat);
    encode_level<200, 16, 20, 32>(sm + OFF_T1, xv * 2.0f, yv * 2.0f, zv * 2.0f, feat);
    encode_level<400, 8, 12, 48>(sm + OFF_T2, xv * 4.0f, yv * 4.0f, zv * 4.0f, feat);
    encode_level<400, 4, 4, 56>(sm + OFF_T3, xv * 8.0f, yv * 8.0f, zv * 8.0f, feat);
    encode_level<400, 3, 4, 60>(sm + OFF_T4, __fdiv_rn(xv, 0.05f),
                                __fdiv_rn(yv, 0.05f), __fdiv_rn(zv, 0.05f), feat);

#pragma unroll
    for (int k = 0; k < 63; k++) sm[OFF_FT + k * FT_STRIDE + tid] = feat[k];
    __syncthreads();

    // ---- phase 2: fused dual-head GEMM + epilogues --------------------------
    const int pg = tid >> 3;   // 8-point group
    const int cg = tid & 7;    // 8-col group
    const int base_pt = blockIdx.x * PTS + pg * 8;

    unsigned long long accD[4][8], accC[4][8];
    gemm_tile2(sm, pg, cg, accD, accC);

    // ===== head D epilogue =====
    {
        const float4* w4 = (const float4*)(sm + OFF_W2D + cg * 8);
        float4 w_lo = w4[0], w_hi = w4[1];
        float w2[8] = {w_lo.x, w_lo.y, w_lo.z, w_lo.w, w_hi.x, w_hi.y, w_hi.z, w_hi.w};

        float pd[8];
#pragma unroll
        for (int p = 0; p < 8; p++) pd[p] = 0.0f;
#pragma unroll
        for (int pp = 0; pp < 4; pp++) {
#pragma unroll
            for (int c = 0; c < 8; c++) {
                float h0, h1;
                upk2(accD[pp][c], h0, h1);
                pd[2 * pp + 0] = fmaf(fmaxf(h0, 0.0f), w2[c], pd[2 * pp + 0]);
                pd[2 * pp + 1] = fmaf(fmaxf(h1, 0.0f), w2[c], pd[2 * pp + 1]);
            }
        }
#pragma unroll
        for (int p = 0; p < 8; p++) {
            pd[p] += __shfl_xor_sync(0xffffffffu, pd[p], 1);
            pd[p] += __shfl_xor_sync(0xffffffffu, pd[p], 2);
            pd[p] += __shfl_xor_sync(0xffffffffu, pd[p], 4);
        }
        if (cg == 0) {
            const float b2 = bd2[0];
#pragma unroll
            for (int p = 0; p < 8; p++) {
                int pt = base_pt + p;
                if (pt < N) out[pt] = pd[p] + b2;
            }
        }
    }

    // ===== head C epilogue =====
    {
        float w2[3][8];
#pragma unroll
        for (int ch = 0; ch < 3; ch++) {
            const float4* w4 = (const float4*)(sm + OFF_W2C + ch * 64 + cg * 8);
            float4 w_lo = w4[0], w_hi = w4[1];
            w2[ch][0] = w_lo.x; w2[ch][1] = w_lo.y; w2[ch][2] = w_lo.z; w2[ch][3] = w_lo.w;
            w2[ch][4] = w_hi.x; w2[ch][5] = w_hi.y; w2[ch][6] = w_hi.z; w2[ch][7] = w_hi.w;
        }

        float pc[3][8];
#pragma unroll
        for (int ch = 0; ch < 3; ch++)
#pragma unroll
            for (int p = 0; p < 8; p++) pc[ch][p] = 0.0f;

#pragma unroll
        for (int pp = 0; pp < 4; pp++) {
#pragma unroll
            for (int c = 0; c < 8; c++) {
                float h0, h1;
                upk2(accC[pp][c], h0, h1);
                h0 = fmaxf(h0, 0.0f);
                h1 = fmaxf(h1, 0.0f);
#pragma unroll
                for (int ch = 0; ch < 3; ch++) {
                    pc[ch][2 * pp + 0] = fmaf(h0, w2[ch][c], pc[ch][2 * pp + 0]);
                    pc[ch][2 * pp + 1] = fmaf(h1, w2[ch][c], pc[ch][2 * pp + 1]);
                }
            }
        }
#pragma unroll
        for (int ch = 0; ch < 3; ch++)
#pragma unroll
            for (int p = 0; p < 8; p++) {
                pc[ch][p] += __shfl_xor_sync(0xffffffffu, pc[ch][p], 1);
                pc[ch][p] += __shfl_xor_sync(0xffffffffu, pc[ch][p], 2);
                pc[ch][p] += __shfl_xor_sync(0xffffffffu, pc[ch][p], 4);
            }
        if (cg == 0) {
            const float b0 = bc2[0], b1v = bc2[1], b2v = bc2[2];
#pragma unroll
            for (int p = 0; p < 8; p++) {
                int pt = base_pt + p;
                if (pt < N) {
                    out[N + pt * 3 + 0] = pc[0][p] + b0;
                    out[N + pt * 3 + 1] = pc[1][p] + b1v;
                    out[N + pt * 3 + 2] = pc[2][p] + b2v;
                }
            }
        }
    }
}

extern "C" void kernel_launch(void* const* d_in, const int* in_sizes, int n_in,
                              void* d_out, int out_size) {
    const float* x = (const float*)d_in[0];
    const float* e0 = (const float*)d_in[1];
    const float* e1 = (const float*)d_in[2];
    const float* e2 = (const float*)d_in[3];
    const float* e3 = (const float*)d_in[4];
    const float* e4 = (const float*)d_in[5];
    const float* Wd1 = (const float*)d_in[6];
    const float* bd1 = (const float*)d_in[7];
    const float* Wd2 = (const float*)d_in[8];
    const float* bd2 = (const float*)d_in[9];
    const float* Wc1 = (const float*)d_in[10];
    const float* bc1 = (const float*)d_in[11];
    const float* Wc2 = (const float*)d_in[12];
    const float* bc2 = (const float*)d_in[13];

    const int N = in_sizes[0] / 3;
    float* out = (float*)d_out;

    cudaFuncSetAttribute(nerf_fused_kernel,
                         cudaFuncAttributeMaxDynamicSharedMemorySize, SMEM_BYTES);

    const int grid = (N + PTS - 1) / PTS;
    nerf_fused_kernel<<<grid, NTHREADS, SMEM_BYTES>>>(
        x, e0, e1, e2, e3, e4, Wd1, bd1, Wd2, bd2, Wc1, bc1, Wc2, bc2, out, N);
}